// round 1
// baseline (speedup 1.0000x reference)
#include <cuda_runtime.h>

// SparseLinearV: y = scatter(W_coo) @ x + bias
//   W: (4096 x 4096) scattered from COO (rows, cols, vals), duplicates accumulate
//   x: (4096 x 4096) fp32, y: (4096 x 4096) fp32, bias broadcast over last axis.
//
// Strategy: densify W into a __device__ global (64 MB), then tiled SIMT SGEMM.
// (Sparse SpMM is L2-traffic-bound at >=2.5ms; dense GEMM is the faster path
//  and sets up the tensor-core port in later rounds.)

#define IN_F   4096
#define OUT_F  4096
#define NCOLS  4096

// 64 MB scratch for the densified weight matrix (allocation-free rule:
// __device__ globals are the sanctioned scratch mechanism).
__device__ float g_W[(size_t)IN_F * OUT_F];

// ---------------------------------------------------------------------------
// Kernel 1: zero W (d_out & g_W are not guaranteed zeroed; poisoned to 0xAA)
// ---------------------------------------------------------------------------
__global__ void zero_W_kernel() {
    size_t n4 = (size_t)IN_F * OUT_F / 4;
    float4 z = make_float4(0.f, 0.f, 0.f, 0.f);
    float4* p = reinterpret_cast<float4*>(g_W);
    for (size_t i = (size_t)blockIdx.x * blockDim.x + threadIdx.x;
         i < n4; i += (size_t)gridDim.x * blockDim.x)
        p[i] = z;
}

// ---------------------------------------------------------------------------
// Kernel 2: COO scatter with accumulation (atomicAdd; ~1.68M mostly-distinct
// addresses -> REDG spread-addr path, fast)
// ---------------------------------------------------------------------------
__global__ void scatter_kernel(const int* __restrict__ rows,
                               const int* __restrict__ cols,
                               const float* __restrict__ vals,
                               int nnz) {
    int i = blockIdx.x * blockDim.x + threadIdx.x;
    if (i < nnz) {
        atomicAdd(&g_W[(size_t)rows[i] * OUT_F + cols[i]], vals[i]);
    }
}

// ---------------------------------------------------------------------------
// Kernel 3: tiled SGEMM  C = W @ x + bias
//   BM=BN=128, BK=16, 256 threads, 8x8 microtile per thread.
// ---------------------------------------------------------------------------
#define BM 128
#define BN 128
#define BK 16
#define TM 8
#define TN 8

__global__ __launch_bounds__(256, 2)
void sgemm_bias_kernel(const float* __restrict__ B,   // x: (K=4096, N=4096)
                       const float* __restrict__ bias,
                       float* __restrict__ C) {       // y: (M=4096, N=4096)
    const int K = IN_F;   // inner dim (W is M x K with M=IN_F? no: W is (IN_F x OUT_F))
    // Dimensions: C(M=IN_F=4096, N=NCOLS=4096) = W(4096 x 4096) @ x(4096 x 4096)
    const int Kdim = OUT_F;   // reduction dim = 4096
    const int N    = NCOLS;
    (void)K;

    __shared__ float As[BK][BM];   // W tile, stored transposed (k-major)
    __shared__ float Bs[BK][BN];   // x tile

    const int tid = threadIdx.x;          // 0..255
    const int tx  = tid & 15;             // 0..15 -> column group
    const int ty  = tid >> 4;             // 0..15 -> row group

    const int rowBase = blockIdx.y * BM;  // M offset
    const int colBase = blockIdx.x * BN;  // N offset

    const float* A = g_W;                 // (M x Kdim), row-major

    float acc[TM][TN];
#pragma unroll
    for (int i = 0; i < TM; i++)
#pragma unroll
        for (int j = 0; j < TN; j++) acc[i][j] = 0.f;

    // Tile-load index precompute.
    // A tile: BM x BK = 128x16 floats = 512 float4. Each thread: 2 float4.
    //   f in [0,512): arow = f >> 2, ak4 = f & 3  (4 float4 per row of 16)
    // B tile: BK x BN = 16x128 floats = 512 float4. Each thread: 2 float4.
    //   f in [0,512): brow = f >> 5, bc4 = f & 31 (32 float4 per row of 128)
    for (int k0 = 0; k0 < Kdim; k0 += BK) {
#pragma unroll
        for (int l = 0; l < 2; l++) {
            int f = tid + l * 256;
            // --- A tile load (transpose into As[k][m]) ---
            int arow = f >> 2;
            int ak4  = f & 3;
            float4 av = *reinterpret_cast<const float4*>(
                &A[(size_t)(rowBase + arow) * Kdim + k0 + ak4 * 4]);
            As[ak4 * 4 + 0][arow] = av.x;
            As[ak4 * 4 + 1][arow] = av.y;
            As[ak4 * 4 + 2][arow] = av.z;
            As[ak4 * 4 + 3][arow] = av.w;
            // --- B tile load (direct) ---
            int brow = f >> 5;
            int bc4  = f & 31;
            float4 bv = *reinterpret_cast<const float4*>(
                &B[(size_t)(k0 + brow) * N + colBase + bc4 * 4]);
            *reinterpret_cast<float4*>(&Bs[brow][bc4 * 4]) = bv;
        }
        __syncthreads();

#pragma unroll
        for (int k = 0; k < BK; k++) {
            float ra[TM], rb[TN];
            // vectorized smem reads (two float4 each)
            float4 a0 = *reinterpret_cast<const float4*>(&As[k][ty * TM + 0]);
            float4 a1 = *reinterpret_cast<const float4*>(&As[k][ty * TM + 4]);
            float4 b0 = *reinterpret_cast<const float4*>(&Bs[k][tx * TN + 0]);
            float4 b1 = *reinterpret_cast<const float4*>(&Bs[k][tx * TN + 4]);
            ra[0]=a0.x; ra[1]=a0.y; ra[2]=a0.z; ra[3]=a0.w;
            ra[4]=a1.x; ra[5]=a1.y; ra[6]=a1.z; ra[7]=a1.w;
            rb[0]=b0.x; rb[1]=b0.y; rb[2]=b0.z; rb[3]=b0.w;
            rb[4]=b1.x; rb[5]=b1.y; rb[6]=b1.z; rb[7]=b1.w;
#pragma unroll
            for (int i = 0; i < TM; i++)
#pragma unroll
                for (int j = 0; j < TN; j++)
                    acc[i][j] = fmaf(ra[i], rb[j], acc[i][j]);
        }
        __syncthreads();
    }

    // Epilogue: add bias (indexed by global column) and store with float4.
#pragma unroll
    for (int i = 0; i < TM; i++) {
        int gr = rowBase + ty * TM + i;
        float4 bia0 = *reinterpret_cast<const float4*>(&bias[colBase + tx * TN + 0]);
        float4 bia1 = *reinterpret_cast<const float4*>(&bias[colBase + tx * TN + 4]);
        float4 o0 = make_float4(acc[i][0] + bia0.x, acc[i][1] + bia0.y,
                                acc[i][2] + bia0.z, acc[i][3] + bia0.w);
        float4 o1 = make_float4(acc[i][4] + bia1.x, acc[i][5] + bia1.y,
                                acc[i][6] + bia1.z, acc[i][7] + bia1.w);
        *reinterpret_cast<float4*>(&C[(size_t)gr * N + colBase + tx * TN + 0]) = o0;
        *reinterpret_cast<float4*>(&C[(size_t)gr * N + colBase + tx * TN + 4]) = o1;
    }
}

// ---------------------------------------------------------------------------
// Launch
// ---------------------------------------------------------------------------
extern "C" void kernel_launch(void* const* d_in, const int* in_sizes, int n_in,
                              void* d_out, int out_size) {
    const float* x    = (const float*)d_in[0];   // (4096, 4096) fp32
    const int*   rows = (const int*)d_in[1];     // (NNZ,) i32
    const int*   cols = (const int*)d_in[2];     // (NNZ,) i32
    const float* vals = (const float*)d_in[3];   // (NNZ,) f32
    const float* bias = (const float*)d_in[4];   // (4096,) f32
    float*       y    = (float*)d_out;           // (4096, 4096) f32
    const int nnz = in_sizes[1];

    // 1) zero the dense W scratch
    zero_W_kernel<<<1184, 256>>>();  // 8 blocks/SM worth of grid; grid-stride

    // 2) scatter COO -> dense (accumulating duplicates)
    scatter_kernel<<<(nnz + 255) / 256, 256>>>(rows, cols, vals, nnz);

    // 3) dense GEMM + bias
    dim3 grid(NCOLS / BN, IN_F / BM);  // 32 x 32
    sgemm_bias_kernel<<<grid, 256>>>(x, bias, y);
}

// round 2
// speedup vs baseline: 3.9979x; 3.9979x over previous
#include <cuda_runtime.h>

// SparseLinearV: y = scatter(W_coo) @ x + bias
// Round 2: densify W (zero + atomic scatter), then tf32 tensor-core GEMM
// via mma.sync.m16n8k8 with cp.async double-buffered pipeline.

#define IN_F   4096
#define OUT_F  4096
#define NCOLS  4096

// 64 MB scratch for the densified weight matrix.
__device__ float g_W[(size_t)IN_F * OUT_F];

// ---------------------------------------------------------------------------
// Kernel 1: zero W
// ---------------------------------------------------------------------------
__global__ void zero_W_kernel() {
    size_t n4 = (size_t)IN_F * OUT_F / 4;
    float4 z = make_float4(0.f, 0.f, 0.f, 0.f);
    float4* p = reinterpret_cast<float4*>(g_W);
    for (size_t i = (size_t)blockIdx.x * blockDim.x + threadIdx.x;
         i < n4; i += (size_t)gridDim.x * blockDim.x)
        p[i] = z;
}

// ---------------------------------------------------------------------------
// Kernel 2: COO scatter with accumulation
// ---------------------------------------------------------------------------
__global__ void scatter_kernel(const int* __restrict__ rows,
                               const int* __restrict__ cols,
                               const float* __restrict__ vals,
                               int nnz) {
    int i = blockIdx.x * blockDim.x + threadIdx.x;
    if (i < nnz) {
        atomicAdd(&g_W[(size_t)rows[i] * OUT_F + cols[i]], vals[i]);
    }
}

// ---------------------------------------------------------------------------
// tf32 tensor-core GEMM:  C(4096x4096) = g_W @ x + bias
// ---------------------------------------------------------------------------
#define BM 128
#define BN 128
#define BK 16
#define AS_STRIDE 20    // m-major A tile stride (floats): conflict-free frag LDS
#define BS_STRIDE 136   // k-major B tile stride (floats): conflict-free frag LDS

__device__ __forceinline__ unsigned f2tf(float x) {
    unsigned r;
    asm("cvt.rna.tf32.f32 %0, %1;" : "=r"(r) : "f"(x));
    return r;
}

__device__ __forceinline__ void mma_tf32(float c[4], const unsigned a[4], const unsigned b[2]) {
    asm volatile(
        "mma.sync.aligned.m16n8k8.row.col.f32.tf32.tf32.f32 "
        "{%0,%1,%2,%3}, {%4,%5,%6,%7}, {%8,%9}, {%0,%1,%2,%3};"
        : "+f"(c[0]), "+f"(c[1]), "+f"(c[2]), "+f"(c[3])
        : "r"(a[0]), "r"(a[1]), "r"(a[2]), "r"(a[3]),
          "r"(b[0]), "r"(b[1]));
}

__device__ __forceinline__ void cp_async16(void* smem_dst, const void* gsrc) {
    unsigned saddr = (unsigned)__cvta_generic_to_shared(smem_dst);
    asm volatile("cp.async.cg.shared.global [%0], [%1], 16;"
                 :: "r"(saddr), "l"(gsrc));
}
__device__ __forceinline__ void cp_async_commit() {
    asm volatile("cp.async.commit_group;");
}
template<int N> __device__ __forceinline__ void cp_async_wait() {
    asm volatile("cp.async.wait_group %0;" :: "n"(N));
}

__global__ __launch_bounds__(256, 2)
void gemm_tf32_kernel(const float* __restrict__ B,    // x: (K=4096, N=4096)
                      const float* __restrict__ bias,
                      float* __restrict__ C) {        // y: (M=4096, N=4096)
    __shared__ __align__(16) float As[2][BM * AS_STRIDE];   // 2 x 10 KB
    __shared__ __align__(16) float Bs[2][BK * BS_STRIDE];   // 2 x 8.5 KB

    const int tid  = threadIdx.x;
    const int lane = tid & 31;
    const int w    = tid >> 5;        // 0..7
    const int wm   = w & 1;           // 2 M-warps (64 rows each)
    const int wn   = w >> 1;          // 4 N-warps (32 cols each)

    const int rowBase = blockIdx.y * BM;
    const int colBase = blockIdx.x * BN;
    const float* A = g_W;             // (4096 x 4096) row-major

    // Loader indices: A tile 128x16 = 512 float4, B tile 16x128 = 512 float4.
    const int f0 = tid, f1 = tid + 256;
    const int a_r0 = f0 >> 2, a_c0 = (f0 & 3) * 4;
    const int a_r1 = f1 >> 2, a_c1 = (f1 & 3) * 4;
    const int b_r0 = f0 >> 5, b_c0 = (f0 & 31) * 4;
    const int b_r1 = f1 >> 5, b_c1 = (f1 & 31) * 4;

    float acc[4][4][4];
#pragma unroll
    for (int i = 0; i < 4; i++)
#pragma unroll
        for (int j = 0; j < 4; j++)
#pragma unroll
            for (int q = 0; q < 4; q++) acc[i][j][q] = 0.f;

    // Prefetch tile 0.
    {
        cp_async16(&As[0][a_r0 * AS_STRIDE + a_c0], &A[(size_t)(rowBase + a_r0) * OUT_F + a_c0]);
        cp_async16(&As[0][a_r1 * AS_STRIDE + a_c1], &A[(size_t)(rowBase + a_r1) * OUT_F + a_c1]);
        cp_async16(&Bs[0][b_r0 * BS_STRIDE + b_c0], &B[(size_t)(b_r0) * NCOLS + colBase + b_c0]);
        cp_async16(&Bs[0][b_r1 * BS_STRIDE + b_c1], &B[(size_t)(b_r1) * NCOLS + colBase + b_c1]);
        cp_async_commit();
    }

    const int NT = OUT_F / BK;  // 256 k-tiles
    const int r  = lane >> 2;
    const int c  = lane & 3;

    for (int kt = 0; kt < NT; kt++) {
        const int cur = kt & 1;
        if (kt + 1 < NT) {
            const int k0 = (kt + 1) * BK;
            const int nxt = cur ^ 1;
            cp_async16(&As[nxt][a_r0 * AS_STRIDE + a_c0], &A[(size_t)(rowBase + a_r0) * OUT_F + k0 + a_c0]);
            cp_async16(&As[nxt][a_r1 * AS_STRIDE + a_c1], &A[(size_t)(rowBase + a_r1) * OUT_F + k0 + a_c1]);
            cp_async16(&Bs[nxt][b_r0 * BS_STRIDE + b_c0], &B[(size_t)(k0 + b_r0) * NCOLS + colBase + b_c0]);
            cp_async16(&Bs[nxt][b_r1 * BS_STRIDE + b_c1], &B[(size_t)(k0 + b_r1) * NCOLS + colBase + b_c1]);
            cp_async_commit();
            cp_async_wait<1>();   // tile kt complete
        } else {
            cp_async_wait<0>();
        }
        __syncthreads();

#pragma unroll
        for (int ks = 0; ks < 2; ks++) {
            const int k8 = ks * 8;
            unsigned afr[4][4], bfr[4][2];
            const float* Ab = &As[cur][0];
            const float* Bb = &Bs[cur][0];
#pragma unroll
            for (int i = 0; i < 4; i++) {
                const int m = wm * 64 + i * 16 + r;
                afr[i][0] = f2tf(Ab[(m)     * AS_STRIDE + k8 + c]);
                afr[i][1] = f2tf(Ab[(m + 8) * AS_STRIDE + k8 + c]);
                afr[i][2] = f2tf(Ab[(m)     * AS_STRIDE + k8 + c + 4]);
                afr[i][3] = f2tf(Ab[(m + 8) * AS_STRIDE + k8 + c + 4]);
            }
#pragma unroll
            for (int j = 0; j < 4; j++) {
                const int n = wn * 32 + j * 8 + r;
                bfr[j][0] = f2tf(Bb[(k8 + c)     * BS_STRIDE + n]);
                bfr[j][1] = f2tf(Bb[(k8 + c + 4) * BS_STRIDE + n]);
            }
#pragma unroll
            for (int i = 0; i < 4; i++)
#pragma unroll
                for (int j = 0; j < 4; j++)
                    mma_tf32(acc[i][j], afr[i], bfr[j]);
        }
        __syncthreads();
    }

    // Epilogue: c0,c1 -> (row, col), (row, col+1); c2,c3 -> (row+8, ...)
    const int c2 = (lane & 3) * 2;
#pragma unroll
    for (int i = 0; i < 4; i++) {
#pragma unroll
        for (int j = 0; j < 4; j++) {
            const int col  = colBase + wn * 32 + j * 8 + c2;
            const int row0 = rowBase + wm * 64 + i * 16 + r;
            const float b0 = bias[col];
            const float b1 = bias[col + 1];
            float2 o0 = make_float2(acc[i][j][0] + b0, acc[i][j][1] + b1);
            float2 o1 = make_float2(acc[i][j][2] + b0, acc[i][j][3] + b1);
            *reinterpret_cast<float2*>(&C[(size_t)row0 * NCOLS + col])       = o0;
            *reinterpret_cast<float2*>(&C[(size_t)(row0 + 8) * NCOLS + col]) = o1;
        }
    }
}

// ---------------------------------------------------------------------------
// Launch
// ---------------------------------------------------------------------------
extern "C" void kernel_launch(void* const* d_in, const int* in_sizes, int n_in,
                              void* d_out, int out_size) {
    const float* x    = (const float*)d_in[0];
    const int*   rows = (const int*)d_in[1];
    const int*   cols = (const int*)d_in[2];
    const float* vals = (const float*)d_in[3];
    const float* bias = (const float*)d_in[4];
    float*       y    = (float*)d_out;
    const int nnz = in_sizes[1];

    zero_W_kernel<<<1184, 256>>>();
    scatter_kernel<<<(nnz + 255) / 256, 256>>>(rows, cols, vals, nnz);

    dim3 grid(NCOLS / BN, IN_F / BM);  // 32 x 32
    gemm_tf32_kernel<<<grid, 256>>>(x, bias, y);
}